// round 15
// baseline (speedup 1.0000x reference)
#include <cuda_runtime.h>
#include <cuda_fp16.h>
#include <cstdint>
#include <math.h>

// ---------------- problem constants ----------------
#define Bz    32
#define Hh    56
#define Ww    56
#define Cc    384
#define HEADS 12
#define DH    32
#define WIN   7
#define SHIFT 3
#define NN    49
#define NWIN  64
#define HID   1536
#define NTOK  (Bz*Hh*Ww)            // 100352
#define SCALE 0.1767766952966369f

typedef __half f16;

// ---------------- scratch (static device globals) ---------------------------
__device__ f16   g_a   [(size_t)NTOK * Cc];      // fp16 A (LN1/attn/LN2 out, time-shared)
__device__ f16   g_f   [(size_t)NTOK * HID];     // FC1 output (gelu'd, fp16)
__device__ f16   g_qkvh[(size_t)NTOK * 3 * Cc];  // qkv fp16
__device__ f16   g_x1h [(size_t)NTOK * Cc];      // residual stream x1 (fp16)
__device__ float g_tbl [4 * HEADS * 64 * 64];    // combined bias+mask tables
// transposed fp16 weights [N][K]
#define WOFF_QKV  0
#define WOFF_PROJ (WOFF_QKV  + 1152*384)
#define WOFF_FC1  (WOFF_PROJ + 384*384)
#define WOFF_FC2  (WOFF_FC1  + 1536*384)
#define WTOT      (WOFF_FC2  + 384*1536)
__device__ f16 g_w[WTOT];

#define NE_QKV  (1152*384)
#define NE_PROJ (384*384)
#define NE_FC1  (384*1536)
#define NE_FC2  (1536*384)
#define NE_TOT  (NE_QKV + NE_PROJ + NE_FC1 + NE_FC2)

// ---------------- helpers ---------------------------------------------------
__device__ __forceinline__ uint32_t smem_u32(const void* p) {
    uint32_t a;
    asm("{ .reg .u64 t; cvta.to.shared.u64 t, %1; cvt.u32.u64 %0, t; }" : "=r"(a) : "l"(p));
    return a;
}
__device__ __forceinline__ void cp16(uint32_t dst, const void* src) {
    asm volatile("cp.async.cg.shared.global [%0], [%1], 16;" :: "r"(dst), "l"(src));
}
#define CP_COMMIT()  asm volatile("cp.async.commit_group;" ::: "memory")
#define CP_WAIT(n)   asm volatile("cp.async.wait_group %0;" :: "n"(n) : "memory")
#define LDSM4(r, addr) \
    asm volatile("ldmatrix.sync.aligned.m8n8.x4.shared.b16 {%0,%1,%2,%3}, [%4];" \
        : "=r"((r)[0]), "=r"((r)[1]), "=r"((r)[2]), "=r"((r)[3]) : "r"(addr))
#define LDSM4T(r, addr) \
    asm volatile("ldmatrix.sync.aligned.m8n8.x4.trans.shared.b16 {%0,%1,%2,%3}, [%4];" \
        : "=r"((r)[0]), "=r"((r)[1]), "=r"((r)[2]), "=r"((r)[3]) : "r"(addr))
__device__ __forceinline__ void mma16816(float* c, const uint32_t* a, const uint32_t* b) {
    asm volatile("mma.sync.aligned.m16n8k16.row.col.f32.f16.f16.f32 "
        "{%0,%1,%2,%3}, {%4,%5,%6,%7}, {%8,%9}, {%0,%1,%2,%3};"
        : "+f"(c[0]), "+f"(c[1]), "+f"(c[2]), "+f"(c[3])
        : "r"(a[0]), "r"(a[1]), "r"(a[2]), "r"(a[3]), "r"(b[0]), "r"(b[1]));
}
__device__ __forceinline__ uint32_t pack_h2(float a, float b) {
    __half2 h = __floats2half2_rn(a, b);
    return *reinterpret_cast<uint32_t*>(&h);
}
__device__ __forceinline__ float ld_as_float(const float* p)  { return *p; }
__device__ __forceinline__ float ld_as_float(const f16* p)    { return __half2float(*p); }

// ---------------- fused weight convert+transpose ----------------------------
__global__ void wconv_all(const float* __restrict__ w0, const float* __restrict__ w1,
                          const float* __restrict__ w2, const float* __restrict__ w3,
                          f16* __restrict__ o)
{
    int idx = blockIdx.x * 256 + threadIdx.x;
    if (idx >= NE_TOT) return;
    const float* src; int K, N, base, loc;
    if (idx < NE_QKV)                    { src = w0; K = 384;  N = 1152; base = WOFF_QKV;  loc = idx; }
    else if (idx < NE_QKV + NE_PROJ)     { src = w1; K = 384;  N = 384;  base = WOFF_PROJ; loc = idx - NE_QKV; }
    else if (idx < NE_QKV + NE_PROJ + NE_FC1)
                                         { src = w2; K = 384;  N = 1536; base = WOFF_FC1;  loc = idx - NE_QKV - NE_PROJ; }
    else                                 { src = w3; K = 1536; N = 384;  base = WOFF_FC2;  loc = idx - NE_QKV - NE_PROJ - NE_FC1; }
    int n = loc % N, k = loc / N;
    o[(size_t)base + (size_t)n * K + k] = __float2half(src[loc]);
}

// ---------------- combined bias+mask table setup ----------------------------
__global__ void attn_tbl(const float* __restrict__ rpb, float* __restrict__ tbl)
{
    int cls = blockIdx.x / HEADS, hd = blockIdx.x % HEADS;
    int wh = (cls & 2) ? 7 : 0, ww = (cls & 1) ? 7 : 0;
    for (int idx = threadIdx.x; idx < 64 * 64; idx += 256) {
        int i = idx >> 6, j = idx & 63;
        float v;
        if (i >= NN)      v = 0.0f;
        else if (j >= NN) v = -1e30f;
        else {
            int ir = i / WIN, ic = i % WIN, jr = j / WIN, jc = j % WIN;
            int ridx = (ir - jr + WIN - 1) * (2 * WIN - 1) + (ic - jc + WIN - 1);
            v = rpb[ridx * HEADS + hd];
            int hi2 = wh * WIN + ir, wi = ww * WIN + ic;
            int hj  = wh * WIN + jr, wj = ww * WIN + jc;
            int regi = (hi2 < Hh - WIN ? 0 : (hi2 < Hh - SHIFT ? 1 : 2)) * 3
                     + (wi  < Ww - WIN ? 0 : (wi  < Ww - SHIFT ? 1 : 2));
            int regj = (hj  < Hh - WIN ? 0 : (hj  < Hh - SHIFT ? 1 : 2)) * 3
                     + (wj  < Ww - WIN ? 0 : (wj  < Ww - SHIFT ? 1 : 2));
            if (regi != regj) v -= 100.0f;
        }
        tbl[(size_t)blockIdx.x * 4096 + idx] = v;
    }
}

// ---------------- LayerNorm, warp-per-row (4 rows / 128-thread block) -------
template<bool SHIFTED, typename TIN>
__global__ __launch_bounds__(128)
void ln_kernel(const TIN* __restrict__ x, const float* __restrict__ gw,
               const float* __restrict__ gb, f16* __restrict__ o)
{
    int warp = threadIdx.x >> 5, lane = threadIdx.x & 31;
    int row = blockIdx.x * 4 + warp;
    int src;
    if (SHIFTED) {
        int win = row / NN, pos = row % NN;
        int b = win >> 6, wh = (win >> 3) & 7, ww = win & 7;
        int i = pos / WIN, j = pos % WIN;
        int h = (wh * WIN + i + SHIFT) % Hh;
        int w = (ww * WIN + j + SHIFT) % Ww;
        src = (b * Hh + h) * Ww + w;
    } else {
        src = row;
    }
    const TIN* xr = x + (size_t)src * Cc;
    float v[12];
    float s = 0.0f, sq = 0.0f;
    #pragma unroll
    for (int k = 0; k < 12; k++) {
        v[k] = ld_as_float(xr + lane + k * 32);
        s  += v[k];
        sq += v[k] * v[k];
    }
    #pragma unroll
    for (int o2 = 16; o2; o2 >>= 1) {
        s  += __shfl_xor_sync(0xffffffffu, s,  o2);
        sq += __shfl_xor_sync(0xffffffffu, sq, o2);
    }
    float mean = s * (1.0f / Cc);
    float var  = sq * (1.0f / Cc) - mean * mean;
    float rstd = rsqrtf(var + 1e-5f);
    size_t ro = (size_t)row * Cc;
    #pragma unroll
    for (int k = 0; k < 12; k++) {
        int c = lane + k * 32;
        o[ro + c] = __float2half((v[k] - mean) * rstd * gw[c] + gb[c]);
    }
}

// ---------------- HMMA GEMM: out[M,N] = A[M,K](f16) @ W^T (W as [N][K] f16) -
// Proven-best R10 config: 128x128 CTA tile, BK=32, ROWB=80, 4 stages. FROZEN.
#define BK      32
#define STAGES  4
#define ROWB    80
#define STG_B   10240
#define STG     20480
#define SMEM_GEMM (STAGES * STG)    // 81920

enum { EPI_BIAS = 0, EPI_GELU = 1, EPI_RES = 2, EPI_SWIN = 3, EPI_BIASH = 4 };

template<int EPI>
__global__ __launch_bounds__(256, 2)
void hgemm(const f16* __restrict__ A, const f16* __restrict__ Bw,
           const float* __restrict__ bias, const float* __restrict__ res,
           const f16* __restrict__ resh,
           float* __restrict__ out, f16* __restrict__ oh,
           int M, int N, int K)
{
    extern __shared__ char smem[];
    uint32_t sb = smem_u32(smem);
    int tid = threadIdx.x, lane = tid & 31, warp = tid >> 5;
    int warpM = warp >> 2, warpN = warp & 3;      // 2 x 4 warp grid
    int mBase = blockIdx.y * 128, nBase = blockIdx.x * 128;
    const int nt = K / BK;

    float acc[4][4][4] = {};

    auto load_tile = [&](int t) {
        uint32_t st = sb + (t % STAGES) * STG;
        int k0 = t * BK;
        #pragma unroll
        for (int i = 0; i < 2; i++) {
            int ci = i * 256 + tid;
            int row = ci >> 2, c = ci & 3;
            cp16(st + row * ROWB + c * 16,
                 A + (size_t)(mBase + row) * K + k0 + c * 8);
        }
        #pragma unroll
        for (int i = 0; i < 2; i++) {
            int ci = i * 256 + tid;
            int row = ci >> 2, c = ci & 3;
            cp16(st + STG_B + row * ROWB + c * 16,
                 Bw + (size_t)(nBase + row) * K + k0 + c * 8);
        }
        CP_COMMIT();
    };

    load_tile(0);
    load_tile(1);
    load_tile(2);

    int aRow = warpM * 64 + (lane & 15);
    int aKb  = (lane >> 4) << 4;
    int bRow = warpN * 32 + ((lane >> 4) << 3) + (lane & 7);
    int bKb  = (lane & 8) << 1;

    for (int t = 0; t < nt; t++) {
        CP_WAIT(2);
        __syncthreads();
        if (t + 3 < nt) load_tile(t + 3);
        else            CP_COMMIT();            // keep group count invariant
        uint32_t st = sb + (t % STAGES) * STG;
        #pragma unroll
        for (int s = 0; s < 2; s++) {
            uint32_t a[4][4], b[4][2];
            #pragma unroll
            for (int i = 0; i < 4; i++) {
                uint32_t ad = st + (uint32_t)(aRow + i * 16) * ROWB + s * 32 + aKb;
                LDSM4(a[i], ad);
            }
            #pragma unroll
            for (int nf = 0; nf < 2; nf++) {
                uint32_t bt[4];
                uint32_t ad = st + STG_B + (uint32_t)(bRow + nf * 16) * ROWB + s * 32 + bKb;
                LDSM4(bt, ad);
                b[2*nf][0] = bt[0]; b[2*nf][1] = bt[1];
                b[2*nf+1][0] = bt[2]; b[2*nf+1][1] = bt[3];
            }
            #pragma unroll
            for (int i = 0; i < 4; i++)
                #pragma unroll
                for (int j = 0; j < 4; j++)
                    mma16816(acc[i][j], a[i], b[j]);
        }
    }

    // epilogue from registers
    int rBase = mBase + warpM * 64 + (lane >> 2);
    int cBase = nBase + warpN * 32 + (lane & 3) * 2;
    #pragma unroll
    for (int i = 0; i < 4; i++) {
        #pragma unroll
        for (int hh = 0; hh < 2; hh++) {
            int row = rBase + i * 16 + hh * 8;
            size_t orow;
            if (EPI == EPI_SWIN) {
                int win = row / NN, pos = row % NN;
                int b = win >> 6, wh = (win >> 3) & 7, ww = win & 7;
                int i2 = pos / WIN, j2 = pos % WIN;
                int h = (wh * WIN + i2 + SHIFT) % Hh;
                int w = (ww * WIN + j2 + SHIFT) % Ww;
                orow = (size_t)((b * Hh + h) * Ww + w);
            } else {
                orow = (size_t)row;
            }
            #pragma unroll
            for (int j = 0; j < 4; j++) {
                int col = cBase + j * 8;
                float v0 = acc[i][j][hh * 2 + 0] + bias[col];
                float v1 = acc[i][j][hh * 2 + 1] + bias[col + 1];
                if (EPI == EPI_GELU) {
                    v0 = 0.5f * v0 * (1.0f + erff(v0 * 0.70710678118654752f));
                    v1 = 0.5f * v1 * (1.0f + erff(v1 * 0.70710678118654752f));
                    *reinterpret_cast<__half2*>(&oh[orow * N + col]) =
                        __floats2half2_rn(v0, v1);
                } else if (EPI == EPI_BIASH) {
                    *reinterpret_cast<__half2*>(&oh[orow * N + col]) =
                        __floats2half2_rn(v0, v1);
                } else if (EPI == EPI_SWIN) {
                    const float2 r = *reinterpret_cast<const float2*>(&res[orow * Cc + col]);
                    v0 += r.x; v1 += r.y;
                    *reinterpret_cast<__half2*>(&oh[orow * N + col]) =
                        __floats2half2_rn(v0, v1);
                } else {
                    if (EPI == EPI_RES) {
                        __half2 rh = *reinterpret_cast<const __half2*>(&resh[orow * N + col]);
                        float2 rf = __half22float2(rh);
                        v0 += rf.x; v1 += rf.y;
                    }
                    float2 o2; o2.x = v0; o2.y = v1;
                    *reinterpret_cast<float2*>(&out[orow * N + col]) = o2;
                }
            }
        }
    }
}

// ---------------- windowed attention: 2 heads per block ----------------------
// 256 threads = 8 warps; warps 0-3 handle head 2*bx, warps 4-7 head 2*bx+1.
// Each head group uses its own 15360B smem slice; one shared __syncthreads.
#define AVS 0
#define AQS 5120
#define AKS 10240
#define AHDS 15360   // per-head-group smem slice size

__global__ __launch_bounds__(256)
void attn_kernel(const f16* __restrict__ qkv, const float* __restrict__ tbl,
                 f16* __restrict__ o)
{
    __shared__ __align__(16) char sm[2 * AHDS];
    uint32_t sb0 = smem_u32(sm);
    int win = blockIdx.y;
    int wh = (win >> 3) & 7, ww = win & 7;
    int cls = ((wh == 7) ? 2 : 0) | ((ww == 7) ? 1 : 0);
    int tid = threadIdx.x, lane = tid & 31, warp = tid >> 5;
    int hg = tid >> 7;              // head group 0/1 (== warp >> 2)
    int w  = warp & 3;              // role warp within head group
    int hd = blockIdx.x * 2 + hg;
    uint32_t sb = sb0 + hg * AHDS;

    // ---- load q/k/v for this head (49 rows x 32 halves), zero pad ----
    {
        int htid = tid & 127;
        const f16* base = qkv + (size_t)win * NN * (3 * Cc) + hd * DH;
        #pragma unroll
        for (int it = 0; it < 6; it++) {
            int idx = it * 128 + htid;          // 0..767
            int mat = idx >> 8, loc = idx & 255;
            int row = loc >> 2, ch = loc & 3;
            int soff = (mat == 0) ? AQS : (mat == 1) ? AKS : AVS;
            uint4 val = make_uint4(0u, 0u, 0u, 0u);
            if (row < NN)
                val = *reinterpret_cast<const uint4*>(base + (size_t)row * (3 * Cc) + mat * Cc + ch * 8);
            *reinterpret_cast<uint4*>(reinterpret_cast<char*>(sm) + hg * AHDS + soff + row * 80 + ch * 16) = val;
        }
    }
    __syncthreads();

    // ---- S = Q @ K^T ----
    float acc[8][4] = {};
    #pragma unroll
    for (int s = 0; s < 2; s++) {
        uint32_t a[4];
        LDSM4(a, sb + AQS + (uint32_t)(w * 16 + (lane & 15)) * 80 + ((lane >> 4) << 4) + s * 32);
        #pragma unroll
        for (int nf = 0; nf < 4; nf++) {
            uint32_t b[4];
            LDSM4(b, sb + AKS + (uint32_t)(nf * 16 + ((lane >> 4) << 3) + (lane & 7)) * 80
                        + ((lane & 8) << 1) + s * 32);
            mma16816(acc[2 * nf],     a, b);
            mma16816(acc[2 * nf + 1], a, b + 2);
        }
    }

    // ---- scale + bias + mask from table ----
    {
        const float2* tb = reinterpret_cast<const float2*>(
            tbl + ((size_t)(cls * HEADS + hd) << 12));
        int r0 = w * 16 + (lane >> 2), cq = lane & 3;
        #pragma unroll
        for (int j = 0; j < 8; j++) {
            float2 t0 = tb[r0 * 32 + j * 4 + cq];
            float2 t1 = tb[(r0 + 8) * 32 + j * 4 + cq];
            acc[j][0] = fmaf(acc[j][0], SCALE, t0.x);
            acc[j][1] = fmaf(acc[j][1], SCALE, t0.y);
            acc[j][2] = fmaf(acc[j][2], SCALE, t1.x);
            acc[j][3] = fmaf(acc[j][3], SCALE, t1.y);
        }
    }

    // ---- softmax in registers ----
    #pragma unroll
    for (int hh = 0; hh < 2; hh++) {
        float mx = -1e30f;
        #pragma unroll
        for (int j = 0; j < 8; j++)
            mx = fmaxf(mx, fmaxf(acc[j][2 * hh], acc[j][2 * hh + 1]));
        mx = fmaxf(mx, __shfl_xor_sync(0xffffffffu, mx, 1));
        mx = fmaxf(mx, __shfl_xor_sync(0xffffffffu, mx, 2));
        float sum = 0.0f;
        #pragma unroll
        for (int j = 0; j < 8; j++) {
            float e0 = __expf(acc[j][2 * hh]     - mx);
            float e1 = __expf(acc[j][2 * hh + 1] - mx);
            acc[j][2 * hh] = e0; acc[j][2 * hh + 1] = e1;
            sum += e0 + e1;
        }
        sum += __shfl_xor_sync(0xffffffffu, sum, 1);
        sum += __shfl_xor_sync(0xffffffffu, sum, 2);
        float inv = 1.0f / sum;
        #pragma unroll
        for (int j = 0; j < 8; j++) {
            acc[j][2 * hh] *= inv; acc[j][2 * hh + 1] *= inv;
        }
    }

    // ---- repack P: C-fragment (f32) -> A-fragment (f16) ----
    uint32_t pa[4][4];
    #pragma unroll
    for (int jj = 0; jj < 4; jj++) {
        pa[jj][0] = pack_h2(acc[2 * jj][0],     acc[2 * jj][1]);
        pa[jj][1] = pack_h2(acc[2 * jj][2],     acc[2 * jj][3]);
        pa[jj][2] = pack_h2(acc[2 * jj + 1][0], acc[2 * jj + 1][1]);
        pa[jj][3] = pack_h2(acc[2 * jj + 1][2], acc[2 * jj + 1][3]);
    }

    // ---- O = P @ V ----
    float oc[4][4] = {};
    int g = lane >> 3;
    #pragma unroll
    for (int ks = 0; ks < 4; ks++) {
        #pragma unroll
        for (int ng = 0; ng < 2; ng++) {
            uint32_t b[4];
            LDSM4T(b, sb + AVS + (uint32_t)(ks * 16 + (g & 1) * 8 + (lane & 7)) * 80
                         + (ng * 16 + (g >> 1) * 8) * 2);
            mma16816(oc[2 * ng],     pa[ks], b);
            mma16816(oc[2 * ng + 1], pa[ks], b + 2);
        }
    }

    // ---- write output ----
    {
        f16* ob = o + (size_t)win * NN * Cc + hd * DH;
        int r0 = w * 16 + (lane >> 2), c0 = (lane & 3) * 2;
        #pragma unroll
        for (int hh = 0; hh < 2; hh++) {
            int row = r0 + hh * 8;
            if (row < NN) {
                #pragma unroll
                for (int j = 0; j < 4; j++) {
                    __half2 hv = __floats2half2_rn(oc[j][hh * 2], oc[j][hh * 2 + 1]);
                    *reinterpret_cast<__half2*>(ob + (size_t)row * Cc + j * 8 + c0) = hv;
                }
            }
        }
    }
}

// ---------------- launcher --------------------------------------------------
extern "C" void kernel_launch(void* const* d_in, const int* in_sizes, int n_in,
                              void* d_out, int out_size)
{
    const float* x      = (const float*)d_in[0];
    const float* n1w    = (const float*)d_in[1];
    const float* n1b    = (const float*)d_in[2];
    const float* qkv_w  = (const float*)d_in[3];
    const float* qkv_b  = (const float*)d_in[4];
    const float* proj_w = (const float*)d_in[5];
    const float* proj_b = (const float*)d_in[6];
    const float* rpb    = (const float*)d_in[7];
    const float* n2w    = (const float*)d_in[8];
    const float* n2b    = (const float*)d_in[9];
    const float* fc1_w  = (const float*)d_in[10];
    const float* fc1_b  = (const float*)d_in[11];
    const float* fc2_w  = (const float*)d_in[12];
    const float* fc2_b  = (const float*)d_in[13];
    float* out = (float*)d_out;

    f16 *a, *f, *w, *qkvh, *x1h;
    float *tbl;
    cudaGetSymbolAddress((void**)&a,    g_a);
    cudaGetSymbolAddress((void**)&f,    g_f);
    cudaGetSymbolAddress((void**)&w,    g_w);
    cudaGetSymbolAddress((void**)&qkvh, g_qkvh);
    cudaGetSymbolAddress((void**)&x1h,  g_x1h);
    cudaGetSymbolAddress((void**)&tbl,  g_tbl);

    cudaFuncSetAttribute(hgemm<EPI_BIASH>, cudaFuncAttributeMaxDynamicSharedMemorySize, SMEM_GEMM);
    cudaFuncSetAttribute(hgemm<EPI_SWIN>,  cudaFuncAttributeMaxDynamicSharedMemorySize, SMEM_GEMM);
    cudaFuncSetAttribute(hgemm<EPI_GELU>,  cudaFuncAttributeMaxDynamicSharedMemorySize, SMEM_GEMM);
    cudaFuncSetAttribute(hgemm<EPI_RES>,   cudaFuncAttributeMaxDynamicSharedMemorySize, SMEM_GEMM);

    const int MT = NTOK / 128;  // 784

    // 0) weight converts + bias/mask table
    wconv_all<<<(NE_TOT + 255) / 256, 256>>>(qkv_w, proj_w, fc1_w, fc2_w, w);
    attn_tbl<<<4 * HEADS, 256>>>(rpb, tbl);

    // 1) LN1 + shift + window partition -> fp16 (warp-per-row)
    ln_kernel<true, float><<<NTOK / 4, 128>>>(x, n1w, n1b, a);
    // 2) QKV GEMM -> fp16 qkv (+bias)
    hgemm<EPI_BIASH><<<dim3(1152 / 128, MT), 256, SMEM_GEMM>>>(
        a, w + WOFF_QKV, qkv_b, nullptr, nullptr, nullptr, qkvh, NTOK, 1152, Cc);
    // 3) attention (2 heads/block) -> fp16 (A of proj)
    attn_kernel<<<dim3(HEADS / 2, Bz * NWIN), 256>>>(qkvh, tbl, a);
    // 4) proj GEMM + swin remap + residual(x fp32) -> fp16 x1
    hgemm<EPI_SWIN><<<dim3(Cc / 128, MT), 256, SMEM_GEMM>>>(
        a, w + WOFF_PROJ, proj_b, x, nullptr, nullptr, x1h, NTOK, Cc, Cc);
    // 5) LN2 (fp16 input, warp-per-row) -> fp16
    ln_kernel<false, f16><<<NTOK / 4, 128>>>(x1h, n2w, n2b, a);
    // 6) FC1 GEMM + GELU -> fp16 (A of FC2)
    hgemm<EPI_GELU><<<dim3(HID / 128, MT), 256, SMEM_GEMM>>>(
        a, w + WOFF_FC1, fc1_b, nullptr, nullptr, nullptr, f, NTOK, HID, Cc);
    // 7) FC2 GEMM + residual(x1 fp16) -> fp32 out
    hgemm<EPI_RES><<<dim3(Cc / 128, MT), 256, SMEM_GEMM>>>(
        f, w + WOFF_FC2, fc2_b, nullptr, x1h, out, nullptr, NTOK, Cc, HID);
}

// round 16
// speedup vs baseline: 1.0095x; 1.0095x over previous
#include <cuda_runtime.h>
#include <cuda_fp16.h>
#include <cstdint>
#include <math.h>

// ---------------- problem constants ----------------
#define Bz    32
#define Hh    56
#define Ww    56
#define Cc    384
#define HEADS 12
#define DH    32
#define WIN   7
#define SHIFT 3
#define NN    49
#define NWIN  64
#define HID   1536
#define NTOK  (Bz*Hh*Ww)            // 100352
#define SCALE 0.1767766952966369f

typedef __half f16;

// ---------------- scratch (static device globals) ---------------------------
__device__ f16   g_a   [(size_t)NTOK * Cc];      // fp16 A (LN1/attn/LN2 out, time-shared)
__device__ f16   g_f   [(size_t)NTOK * HID];     // FC1 output (gelu'd, fp16)
__device__ f16   g_qkvh[(size_t)NTOK * 3 * Cc];  // qkv fp16
__device__ f16   g_x1h [(size_t)NTOK * Cc];      // residual stream x1 (fp16)
__device__ float g_tbl [4 * HEADS * 64 * 64];    // combined bias+mask tables
// transposed fp16 weights [N][K]
#define WOFF_QKV  0
#define WOFF_PROJ (WOFF_QKV  + 1152*384)
#define WOFF_FC1  (WOFF_PROJ + 384*384)
#define WOFF_FC2  (WOFF_FC1  + 1536*384)
#define WTOT      (WOFF_FC2  + 384*1536)
__device__ f16 g_w[WTOT];

// ---------------- helpers ---------------------------------------------------
__device__ __forceinline__ uint32_t smem_u32(const void* p) {
    uint32_t a;
    asm("{ .reg .u64 t; cvta.to.shared.u64 t, %1; cvt.u32.u64 %0, t; }" : "=r"(a) : "l"(p));
    return a;
}
__device__ __forceinline__ void cp16(uint32_t dst, const void* src) {
    asm volatile("cp.async.cg.shared.global [%0], [%1], 16;" :: "r"(dst), "l"(src));
}
#define CP_COMMIT()  asm volatile("cp.async.commit_group;" ::: "memory")
#define CP_WAIT(n)   asm volatile("cp.async.wait_group %0;" :: "n"(n) : "memory")
#define LDSM4(r, addr) \
    asm volatile("ldmatrix.sync.aligned.m8n8.x4.shared.b16 {%0,%1,%2,%3}, [%4];" \
        : "=r"((r)[0]), "=r"((r)[1]), "=r"((r)[2]), "=r"((r)[3]) : "r"(addr))
#define LDSM4T(r, addr) \
    asm volatile("ldmatrix.sync.aligned.m8n8.x4.trans.shared.b16 {%0,%1,%2,%3}, [%4];" \
        : "=r"((r)[0]), "=r"((r)[1]), "=r"((r)[2]), "=r"((r)[3]) : "r"(addr))
__device__ __forceinline__ void mma16816(float* c, const uint32_t* a, const uint32_t* b) {
    asm volatile("mma.sync.aligned.m16n8k16.row.col.f32.f16.f16.f32 "
        "{%0,%1,%2,%3}, {%4,%5,%6,%7}, {%8,%9}, {%0,%1,%2,%3};"
        : "+f"(c[0]), "+f"(c[1]), "+f"(c[2]), "+f"(c[3])
        : "r"(a[0]), "r"(a[1]), "r"(a[2]), "r"(a[3]), "r"(b[0]), "r"(b[1]));
}
__device__ __forceinline__ uint32_t pack_h2(float a, float b) {
    __half2 h = __floats2half2_rn(a, b);
    return *reinterpret_cast<uint32_t*>(&h);
}
__device__ __forceinline__ float ld_as_float(const float* p)  { return *p; }
__device__ __forceinline__ float ld_as_float(const f16* p)    { return __half2float(*p); }

// ---------------- tiled weight convert+transpose: [K,N] f32 -> [N,K] f16 ----
// 32x32 smem tile; coalesced reads AND writes; 32x33 padding avoids conflicts.
__global__ __launch_bounds__(256)
void wconv_t(const float* __restrict__ src, f16* __restrict__ dst, int K, int N)
{
    __shared__ f16 tile[32][33];
    int tx = threadIdx.x & 31, ty = threadIdx.x >> 5;   // 32 x 8
    int n0 = blockIdx.x * 32, k0 = blockIdx.y * 32;
    #pragma unroll
    for (int i = 0; i < 32; i += 8) {
        int k = k0 + ty + i, n = n0 + tx;
        tile[ty + i][tx] = __float2half(src[(size_t)k * N + n]);
    }
    __syncthreads();
    #pragma unroll
    for (int i = 0; i < 32; i += 8) {
        int n = n0 + ty + i, k = k0 + tx;
        dst[(size_t)n * K + k] = tile[tx][ty + i];
    }
}

// ---------------- combined bias+mask table setup ----------------------------
__global__ void attn_tbl(const float* __restrict__ rpb, float* __restrict__ tbl)
{
    int cls = blockIdx.x / HEADS, hd = blockIdx.x % HEADS;
    int wh = (cls & 2) ? 7 : 0, ww = (cls & 1) ? 7 : 0;
    for (int idx = threadIdx.x; idx < 64 * 64; idx += 256) {
        int i = idx >> 6, j = idx & 63;
        float v;
        if (i >= NN)      v = 0.0f;
        else if (j >= NN) v = -1e30f;
        else {
            int ir = i / WIN, ic = i % WIN, jr = j / WIN, jc = j % WIN;
            int ridx = (ir - jr + WIN - 1) * (2 * WIN - 1) + (ic - jc + WIN - 1);
            v = rpb[ridx * HEADS + hd];
            int hi2 = wh * WIN + ir, wi = ww * WIN + ic;
            int hj  = wh * WIN + jr, wj = ww * WIN + jc;
            int regi = (hi2 < Hh - WIN ? 0 : (hi2 < Hh - SHIFT ? 1 : 2)) * 3
                     + (wi  < Ww - WIN ? 0 : (wi  < Ww - SHIFT ? 1 : 2));
            int regj = (hj  < Hh - WIN ? 0 : (hj  < Hh - SHIFT ? 1 : 2)) * 3
                     + (wj  < Ww - WIN ? 0 : (wj  < Ww - SHIFT ? 1 : 2));
            if (regi != regj) v -= 100.0f;
        }
        tbl[(size_t)blockIdx.x * 4096 + idx] = v;
    }
}

// ---------------- LayerNorm, warp-per-row (4 rows / 128-thread block) -------
template<bool SHIFTED, typename TIN>
__global__ __launch_bounds__(128)
void ln_kernel(const TIN* __restrict__ x, const float* __restrict__ gw,
               const float* __restrict__ gb, f16* __restrict__ o)
{
    int warp = threadIdx.x >> 5, lane = threadIdx.x & 31;
    int row = blockIdx.x * 4 + warp;
    int src;
    if (SHIFTED) {
        int win = row / NN, pos = row % NN;
        int b = win >> 6, wh = (win >> 3) & 7, ww = win & 7;
        int i = pos / WIN, j = pos % WIN;
        int h = (wh * WIN + i + SHIFT) % Hh;
        int w = (ww * WIN + j + SHIFT) % Ww;
        src = (b * Hh + h) * Ww + w;
    } else {
        src = row;
    }
    const TIN* xr = x + (size_t)src * Cc;
    float v[12];
    float s = 0.0f, sq = 0.0f;
    #pragma unroll
    for (int k = 0; k < 12; k++) {
        v[k] = ld_as_float(xr + lane + k * 32);
        s  += v[k];
        sq += v[k] * v[k];
    }
    #pragma unroll
    for (int o2 = 16; o2; o2 >>= 1) {
        s  += __shfl_xor_sync(0xffffffffu, s,  o2);
        sq += __shfl_xor_sync(0xffffffffu, sq, o2);
    }
    float mean = s * (1.0f / Cc);
    float var  = sq * (1.0f / Cc) - mean * mean;
    float rstd = rsqrtf(var + 1e-5f);
    size_t ro = (size_t)row * Cc;
    #pragma unroll
    for (int k = 0; k < 12; k++) {
        int c = lane + k * 32;
        o[ro + c] = __float2half((v[k] - mean) * rstd * gw[c] + gb[c]);
    }
}

// ---------------- HMMA GEMM: out[M,N] = A[M,K](f16) @ W^T (W as [N][K] f16) -
// Proven-best R10 config: 128x128 CTA tile, BK=32, ROWB=80, 4 stages. FROZEN.
#define BK      32
#define STAGES  4
#define ROWB    80
#define STG_B   10240
#define STG     20480
#define SMEM_GEMM (STAGES * STG)    // 81920

enum { EPI_BIAS = 0, EPI_GELU = 1, EPI_RES = 2, EPI_SWIN = 3, EPI_BIASH = 4 };

template<int EPI>
__global__ __launch_bounds__(256, 2)
void hgemm(const f16* __restrict__ A, const f16* __restrict__ Bw,
           const float* __restrict__ bias, const float* __restrict__ res,
           const f16* __restrict__ resh,
           float* __restrict__ out, f16* __restrict__ oh,
           int M, int N, int K)
{
    extern __shared__ char smem[];
    uint32_t sb = smem_u32(smem);
    int tid = threadIdx.x, lane = tid & 31, warp = tid >> 5;
    int warpM = warp >> 2, warpN = warp & 3;      // 2 x 4 warp grid
    int mBase = blockIdx.y * 128, nBase = blockIdx.x * 128;
    const int nt = K / BK;

    float acc[4][4][4] = {};

    auto load_tile = [&](int t) {
        uint32_t st = sb + (t % STAGES) * STG;
        int k0 = t * BK;
        #pragma unroll
        for (int i = 0; i < 2; i++) {
            int ci = i * 256 + tid;
            int row = ci >> 2, c = ci & 3;
            cp16(st + row * ROWB + c * 16,
                 A + (size_t)(mBase + row) * K + k0 + c * 8);
        }
        #pragma unroll
        for (int i = 0; i < 2; i++) {
            int ci = i * 256 + tid;
            int row = ci >> 2, c = ci & 3;
            cp16(st + STG_B + row * ROWB + c * 16,
                 Bw + (size_t)(nBase + row) * K + k0 + c * 8);
        }
        CP_COMMIT();
    };

    load_tile(0);
    load_tile(1);
    load_tile(2);

    int aRow = warpM * 64 + (lane & 15);
    int aKb  = (lane >> 4) << 4;
    int bRow = warpN * 32 + ((lane >> 4) << 3) + (lane & 7);
    int bKb  = (lane & 8) << 1;

    for (int t = 0; t < nt; t++) {
        CP_WAIT(2);
        __syncthreads();
        if (t + 3 < nt) load_tile(t + 3);
        else            CP_COMMIT();            // keep group count invariant
        uint32_t st = sb + (t % STAGES) * STG;
        #pragma unroll
        for (int s = 0; s < 2; s++) {
            uint32_t a[4][4], b[4][2];
            #pragma unroll
            for (int i = 0; i < 4; i++) {
                uint32_t ad = st + (uint32_t)(aRow + i * 16) * ROWB + s * 32 + aKb;
                LDSM4(a[i], ad);
            }
            #pragma unroll
            for (int nf = 0; nf < 2; nf++) {
                uint32_t bt[4];
                uint32_t ad = st + STG_B + (uint32_t)(bRow + nf * 16) * ROWB + s * 32 + bKb;
                LDSM4(bt, ad);
                b[2*nf][0] = bt[0]; b[2*nf][1] = bt[1];
                b[2*nf+1][0] = bt[2]; b[2*nf+1][1] = bt[3];
            }
            #pragma unroll
            for (int i = 0; i < 4; i++)
                #pragma unroll
                for (int j = 0; j < 4; j++)
                    mma16816(acc[i][j], a[i], b[j]);
        }
    }

    // epilogue from registers
    int rBase = mBase + warpM * 64 + (lane >> 2);
    int cBase = nBase + warpN * 32 + (lane & 3) * 2;
    #pragma unroll
    for (int i = 0; i < 4; i++) {
        #pragma unroll
        for (int hh = 0; hh < 2; hh++) {
            int row = rBase + i * 16 + hh * 8;
            size_t orow;
            if (EPI == EPI_SWIN) {
                int win = row / NN, pos = row % NN;
                int b = win >> 6, wh = (win >> 3) & 7, ww = win & 7;
                int i2 = pos / WIN, j2 = pos % WIN;
                int h = (wh * WIN + i2 + SHIFT) % Hh;
                int w = (ww * WIN + j2 + SHIFT) % Ww;
                orow = (size_t)((b * Hh + h) * Ww + w);
            } else {
                orow = (size_t)row;
            }
            #pragma unroll
            for (int j = 0; j < 4; j++) {
                int col = cBase + j * 8;
                float v0 = acc[i][j][hh * 2 + 0] + bias[col];
                float v1 = acc[i][j][hh * 2 + 1] + bias[col + 1];
                if (EPI == EPI_GELU) {
                    v0 = 0.5f * v0 * (1.0f + erff(v0 * 0.70710678118654752f));
                    v1 = 0.5f * v1 * (1.0f + erff(v1 * 0.70710678118654752f));
                    *reinterpret_cast<__half2*>(&oh[orow * N + col]) =
                        __floats2half2_rn(v0, v1);
                } else if (EPI == EPI_BIASH) {
                    *reinterpret_cast<__half2*>(&oh[orow * N + col]) =
                        __floats2half2_rn(v0, v1);
                } else if (EPI == EPI_SWIN) {
                    const float2 r = *reinterpret_cast<const float2*>(&res[orow * Cc + col]);
                    v0 += r.x; v1 += r.y;
                    *reinterpret_cast<__half2*>(&oh[orow * N + col]) =
                        __floats2half2_rn(v0, v1);
                } else {
                    if (EPI == EPI_RES) {
                        __half2 rh = *reinterpret_cast<const __half2*>(&resh[orow * N + col]);
                        float2 rf = __half22float2(rh);
                        v0 += rf.x; v1 += rf.y;
                    }
                    float2 o2; o2.x = v0; o2.y = v1;
                    *reinterpret_cast<float2*>(&out[orow * N + col]) = o2;
                }
            }
        }
    }
}

// ---------------- windowed attention: mma + register softmax (R14 best) -----
#define AVS 0
#define AQS 5120
#define AKS 10240

__global__ __launch_bounds__(128)
void attn_kernel(const f16* __restrict__ qkv, const float* __restrict__ tbl,
                 f16* __restrict__ o)
{
    __shared__ __align__(16) char sm[15360];
    uint32_t sb = smem_u32(sm);
    int hd = blockIdx.x, win = blockIdx.y;
    int wh = (win >> 3) & 7, ww = win & 7;
    int cls = ((wh == 7) ? 2 : 0) | ((ww == 7) ? 1 : 0);
    int tid = threadIdx.x, lane = tid & 31, w = tid >> 5;

    // ---- load q/k/v (49 rows x 32 halves), zero pad rows 49..63 ----
    {
        const f16* base = qkv + (size_t)win * NN * (3 * Cc) + hd * DH;
        #pragma unroll
        for (int it = 0; it < 6; it++) {
            int idx = it * 128 + tid;           // 0..767
            int mat = idx >> 8, loc = idx & 255;
            int row = loc >> 2, ch = loc & 3;
            int soff = (mat == 0) ? AQS : (mat == 1) ? AKS : AVS;
            uint4 val = make_uint4(0u, 0u, 0u, 0u);
            if (row < NN)
                val = *reinterpret_cast<const uint4*>(base + (size_t)row * (3 * Cc) + mat * Cc + ch * 8);
            *reinterpret_cast<uint4*>(sm + soff + row * 80 + ch * 16) = val;
        }
    }
    __syncthreads();

    // ---- S = Q @ K^T ----
    float acc[8][4] = {};
    #pragma unroll
    for (int s = 0; s < 2; s++) {
        uint32_t a[4];
        LDSM4(a, sb + AQS + (uint32_t)(w * 16 + (lane & 15)) * 80 + ((lane >> 4) << 4) + s * 32);
        #pragma unroll
        for (int nf = 0; nf < 4; nf++) {
            uint32_t b[4];
            LDSM4(b, sb + AKS + (uint32_t)(nf * 16 + ((lane >> 4) << 3) + (lane & 7)) * 80
                        + ((lane & 8) << 1) + s * 32);
            mma16816(acc[2 * nf],     a, b);
            mma16816(acc[2 * nf + 1], a, b + 2);
        }
    }

    // ---- scale + bias + mask from table ----
    {
        const float2* tb = reinterpret_cast<const float2*>(
            tbl + ((size_t)(cls * HEADS + hd) << 12));
        int r0 = w * 16 + (lane >> 2), cq = lane & 3;
        #pragma unroll
        for (int j = 0; j < 8; j++) {
            float2 t0 = tb[r0 * 32 + j * 4 + cq];
            float2 t1 = tb[(r0 + 8) * 32 + j * 4 + cq];
            acc[j][0] = fmaf(acc[j][0], SCALE, t0.x);
            acc[j][1] = fmaf(acc[j][1], SCALE, t0.y);
            acc[j][2] = fmaf(acc[j][2], SCALE, t1.x);
            acc[j][3] = fmaf(acc[j][3], SCALE, t1.y);
        }
    }

    // ---- softmax in registers ----
    #pragma unroll
    for (int hh = 0; hh < 2; hh++) {
        float mx = -1e30f;
        #pragma unroll
        for (int j = 0; j < 8; j++)
            mx = fmaxf(mx, fmaxf(acc[j][2 * hh], acc[j][2 * hh + 1]));
        mx = fmaxf(mx, __shfl_xor_sync(0xffffffffu, mx, 1));
        mx = fmaxf(mx, __shfl_xor_sync(0xffffffffu, mx, 2));
        float sum = 0.0f;
        #pragma unroll
        for (int j = 0; j < 8; j++) {
            float e0 = __expf(acc[j][2 * hh]     - mx);
            float e1 = __expf(acc[j][2 * hh + 1] - mx);
            acc[j][2 * hh] = e0; acc[j][2 * hh + 1] = e1;
            sum += e0 + e1;
        }
        sum += __shfl_xor_sync(0xffffffffu, sum, 1);
        sum += __shfl_xor_sync(0xffffffffu, sum, 2);
        float inv = 1.0f / sum;
        #pragma unroll
        for (int j = 0; j < 8; j++) {
            acc[j][2 * hh] *= inv; acc[j][2 * hh + 1] *= inv;
        }
    }

    // ---- repack P: C-fragment (f32) -> A-fragment (f16) ----
    uint32_t pa[4][4];
    #pragma unroll
    for (int jj = 0; jj < 4; jj++) {
        pa[jj][0] = pack_h2(acc[2 * jj][0],     acc[2 * jj][1]);
        pa[jj][1] = pack_h2(acc[2 * jj][2],     acc[2 * jj][3]);
        pa[jj][2] = pack_h2(acc[2 * jj + 1][0], acc[2 * jj + 1][1]);
        pa[jj][3] = pack_h2(acc[2 * jj + 1][2], acc[2 * jj + 1][3]);
    }

    // ---- O = P @ V ----
    float oc[4][4] = {};
    int g = lane >> 3;
    #pragma unroll
    for (int ks = 0; ks < 4; ks++) {
        #pragma unroll
        for (int ng = 0; ng < 2; ng++) {
            uint32_t b[4];
            LDSM4T(b, sb + AVS + (uint32_t)(ks * 16 + (g & 1) * 8 + (lane & 7)) * 80
                         + (ng * 16 + (g >> 1) * 8) * 2);
            mma16816(oc[2 * ng],     pa[ks], b);
            mma16816(oc[2 * ng + 1], pa[ks], b + 2);
        }
    }

    // ---- write output ----
    {
        f16* ob = o + (size_t)win * NN * Cc + hd * DH;
        int r0 = w * 16 + (lane >> 2), c0 = (lane & 3) * 2;
        #pragma unroll
        for (int hh = 0; hh < 2; hh++) {
            int row = r0 + hh * 8;
            if (row < NN) {
                #pragma unroll
                for (int j = 0; j < 4; j++) {
                    __half2 hv = __floats2half2_rn(oc[j][hh * 2], oc[j][hh * 2 + 1]);
                    *reinterpret_cast<__half2*>(ob + (size_t)row * Cc + j * 8 + c0) = hv;
                }
            }
        }
    }
}

// ---------------- launcher --------------------------------------------------
extern "C" void kernel_launch(void* const* d_in, const int* in_sizes, int n_in,
                              void* d_out, int out_size)
{
    const float* x      = (const float*)d_in[0];
    const float* n1w    = (const float*)d_in[1];
    const float* n1b    = (const float*)d_in[2];
    const float* qkv_w  = (const float*)d_in[3];
    const float* qkv_b  = (const float*)d_in[4];
    const float* proj_w = (const float*)d_in[5];
    const float* proj_b = (const float*)d_in[6];
    const float* rpb    = (const float*)d_in[7];
    const float* n2w    = (const float*)d_in[8];
    const float* n2b    = (const float*)d_in[9];
    const float* fc1_w  = (const float*)d_in[10];
    const float* fc1_b  = (const float*)d_in[11];
    const float* fc2_w  = (const float*)d_in[12];
    const float* fc2_b  = (const float*)d_in[13];
    float* out = (float*)d_out;

    f16 *a, *f, *w, *qkvh, *x1h;
    float *tbl;
    cudaGetSymbolAddress((void**)&a,    g_a);
    cudaGetSymbolAddress((void**)&f,    g_f);
    cudaGetSymbolAddress((void**)&w,    g_w);
    cudaGetSymbolAddress((void**)&qkvh, g_qkvh);
    cudaGetSymbolAddress((void**)&x1h,  g_x1h);
    cudaGetSymbolAddress((void**)&tbl,  g_tbl);

    cudaFuncSetAttribute(hgemm<EPI_BIASH>, cudaFuncAttributeMaxDynamicSharedMemorySize, SMEM_GEMM);
    cudaFuncSetAttribute(hgemm<EPI_SWIN>,  cudaFuncAttributeMaxDynamicSharedMemorySize, SMEM_GEMM);
    cudaFuncSetAttribute(hgemm<EPI_GELU>,  cudaFuncAttributeMaxDynamicSharedMemorySize, SMEM_GEMM);
    cudaFuncSetAttribute(hgemm<EPI_RES>,   cudaFuncAttributeMaxDynamicSharedMemorySize, SMEM_GEMM);

    const int MT = NTOK / 128;  // 784

    // 0) tiled weight transposes + bias/mask table
    wconv_t<<<dim3(1152 / 32, 384 / 32),  256>>>(qkv_w,  w + WOFF_QKV,  384, 1152);
    wconv_t<<<dim3(384 / 32,  384 / 32),  256>>>(proj_w, w + WOFF_PROJ, 384, 384);
    wconv_t<<<dim3(1536 / 32, 384 / 32),  256>>>(fc1_w,  w + WOFF_FC1,  384, 1536);
    wconv_t<<<dim3(384 / 32,  1536 / 32), 256>>>(fc2_w,  w + WOFF_FC2,  1536, 384);
    attn_tbl<<<4 * HEADS, 256>>>(rpb, tbl);

    // 1) LN1 + shift + window partition -> fp16 (warp-per-row)
    ln_kernel<true, float><<<NTOK / 4, 128>>>(x, n1w, n1b, a);
    // 2) QKV GEMM -> fp16 qkv (+bias)
    hgemm<EPI_BIASH><<<dim3(1152 / 128, MT), 256, SMEM_GEMM>>>(
        a, w + WOFF_QKV, qkv_b, nullptr, nullptr, nullptr, qkvh, NTOK, 1152, Cc);
    // 3) attention (1 head/block, R14 best) -> fp16 (A of proj)
    attn_kernel<<<dim3(HEADS, Bz * NWIN), 128>>>(qkvh, tbl, a);
    // 4) proj GEMM + swin remap + residual(x fp32) -> fp16 x1
    hgemm<EPI_SWIN><<<dim3(Cc / 128, MT), 256, SMEM_GEMM>>>(
        a, w + WOFF_PROJ, proj_b, x, nullptr, nullptr, x1h, NTOK, Cc, Cc);
    // 5) LN2 (fp16 input, warp-per-row) -> fp16
    ln_kernel<false, f16><<<NTOK / 4, 128>>>(x1h, n2w, n2b, a);
    // 6) FC1 GEMM + GELU -> fp16 (A of FC2)
    hgemm<EPI_GELU><<<dim3(HID / 128, MT), 256, SMEM_GEMM>>>(
        a, w + WOFF_FC1, fc1_b, nullptr, nullptr, nullptr, f, NTOK, HID, Cc);
    // 7) FC2 GEMM + residual(x1 fp16) -> fp32 out
    hgemm<EPI_RES><<<dim3(Cc / 128, MT), 256, SMEM_GEMM>>>(
        f, w + WOFF_FC2, fc2_b, nullptr, x1h, out, nullptr, NTOK, Cc, HID);
}

// round 17
// speedup vs baseline: 1.0103x; 1.0008x over previous
#include <cuda_runtime.h>
#include <cuda_fp16.h>
#include <cstdint>
#include <math.h>

// ---------------- problem constants ----------------
#define Bz    32
#define Hh    56
#define Ww    56
#define Cc    384
#define HEADS 12
#define DH    32
#define WIN   7
#define SHIFT 3
#define NN    49
#define NWIN  64
#define HID   1536
#define NTOK  (Bz*Hh*Ww)            // 100352
#define SCALE 0.1767766952966369f

typedef __half f16;

// ---------------- scratch (static device globals) ---------------------------
__device__ f16   g_a   [(size_t)NTOK * Cc];      // fp16 A (LN1/attn/LN2 out, time-shared)
__device__ f16   g_f   [(size_t)NTOK * HID];     // FC1 output (gelu'd, fp16)
__device__ f16   g_qkvh[(size_t)NTOK * 3 * Cc];  // qkv fp16
__device__ f16   g_x1h [(size_t)NTOK * Cc];      // residual stream x1 (fp16)
__device__ float g_tbl [4 * HEADS * 64 * 64];    // combined bias+mask tables
// transposed fp16 weights [N][K]
#define WOFF_QKV  0
#define WOFF_PROJ (WOFF_QKV  + 1152*384)
#define WOFF_FC1  (WOFF_PROJ + 384*384)
#define WOFF_FC2  (WOFF_FC1  + 1536*384)
#define WTOT      (WOFF_FC2  + 384*1536)
__device__ f16 g_w[WTOT];

// tile counts for the fused transpose (32x32 tiles)
#define T_QKV  (36 * 12)    // 432
#define T_PROJ (12 * 12)    // 144
#define T_FC1  (48 * 12)    // 576
#define T_FC2  (12 * 48)    // 576
#define T_TOT  (T_QKV + T_PROJ + T_FC1 + T_FC2)   // 1728

// ---------------- helpers ---------------------------------------------------
__device__ __forceinline__ uint32_t smem_u32(const void* p) {
    uint32_t a;
    asm("{ .reg .u64 t; cvta.to.shared.u64 t, %1; cvt.u32.u64 %0, t; }" : "=r"(a) : "l"(p));
    return a;
}
__device__ __forceinline__ void cp16(uint32_t dst, const void* src) {
    asm volatile("cp.async.cg.shared.global [%0], [%1], 16;" :: "r"(dst), "l"(src));
}
#define CP_COMMIT()  asm volatile("cp.async.commit_group;" ::: "memory")
#define CP_WAIT(n)   asm volatile("cp.async.wait_group %0;" :: "n"(n) : "memory")
#define LDSM4(r, addr) \
    asm volatile("ldmatrix.sync.aligned.m8n8.x4.shared.b16 {%0,%1,%2,%3}, [%4];" \
        : "=r"((r)[0]), "=r"((r)[1]), "=r"((r)[2]), "=r"((r)[3]) : "r"(addr))
#define LDSM4T(r, addr) \
    asm volatile("ldmatrix.sync.aligned.m8n8.x4.trans.shared.b16 {%0,%1,%2,%3}, [%4];" \
        : "=r"((r)[0]), "=r"((r)[1]), "=r"((r)[2]), "=r"((r)[3]) : "r"(addr))
__device__ __forceinline__ void mma16816(float* c, const uint32_t* a, const uint32_t* b) {
    asm volatile("mma.sync.aligned.m16n8k16.row.col.f32.f16.f16.f32 "
        "{%0,%1,%2,%3}, {%4,%5,%6,%7}, {%8,%9}, {%0,%1,%2,%3};"
        : "+f"(c[0]), "+f"(c[1]), "+f"(c[2]), "+f"(c[3])
        : "r"(a[0]), "r"(a[1]), "r"(a[2]), "r"(a[3]), "r"(b[0]), "r"(b[1]));
}
__device__ __forceinline__ uint32_t pack_h2(float a, float b) {
    __half2 h = __floats2half2_rn(a, b);
    return *reinterpret_cast<uint32_t*>(&h);
}
__device__ __forceinline__ float ld_as_float(const float* p)  { return *p; }
__device__ __forceinline__ float ld_as_float(const f16* p)    { return __half2float(*p); }

// ---------------- fused tiled weight transpose: all four weights ------------
// One launch, 1728 tiles of 32x32; coalesced reads AND writes; 32x33 padding.
__global__ __launch_bounds__(256)
void wconv_all(const float* __restrict__ w0, const float* __restrict__ w1,
               const float* __restrict__ w2, const float* __restrict__ w3,
               f16* __restrict__ o)
{
    __shared__ f16 tile[32][33];
    int bid = blockIdx.x;
    const float* src; int K, N, base, nt_x, loc;
    if (bid < T_QKV)                        { src = w0; K = 384;  N = 1152; base = WOFF_QKV;  nt_x = 36; loc = bid; }
    else if (bid < T_QKV + T_PROJ)          { src = w1; K = 384;  N = 384;  base = WOFF_PROJ; nt_x = 12; loc = bid - T_QKV; }
    else if (bid < T_QKV + T_PROJ + T_FC1)  { src = w2; K = 384;  N = 1536; base = WOFF_FC1;  nt_x = 48; loc = bid - T_QKV - T_PROJ; }
    else                                    { src = w3; K = 1536; N = 384;  base = WOFF_FC2;  nt_x = 12; loc = bid - T_QKV - T_PROJ - T_FC1; }
    int n0 = (loc % nt_x) * 32, k0 = (loc / nt_x) * 32;
    int tx = threadIdx.x & 31, ty = threadIdx.x >> 5;   // 32 x 8
    #pragma unroll
    for (int i = 0; i < 32; i += 8) {
        int k = k0 + ty + i, n = n0 + tx;
        tile[ty + i][tx] = __float2half(src[(size_t)k * N + n]);
    }
    __syncthreads();
    f16* dst = o + base;
    #pragma unroll
    for (int i = 0; i < 32; i += 8) {
        int n = n0 + ty + i, k = k0 + tx;
        dst[(size_t)n * K + k] = tile[tx][ty + i];
    }
}

// ---------------- combined bias+mask table setup ----------------------------
__global__ void attn_tbl(const float* __restrict__ rpb, float* __restrict__ tbl)
{
    int cls = blockIdx.x / HEADS, hd = blockIdx.x % HEADS;
    int wh = (cls & 2) ? 7 : 0, ww = (cls & 1) ? 7 : 0;
    for (int idx = threadIdx.x; idx < 64 * 64; idx += 256) {
        int i = idx >> 6, j = idx & 63;
        float v;
        if (i >= NN)      v = 0.0f;
        else if (j >= NN) v = -1e30f;
        else {
            int ir = i / WIN, ic = i % WIN, jr = j / WIN, jc = j % WIN;
            int ridx = (ir - jr + WIN - 1) * (2 * WIN - 1) + (ic - jc + WIN - 1);
            v = rpb[ridx * HEADS + hd];
            int hi2 = wh * WIN + ir, wi = ww * WIN + ic;
            int hj  = wh * WIN + jr, wj = ww * WIN + jc;
            int regi = (hi2 < Hh - WIN ? 0 : (hi2 < Hh - SHIFT ? 1 : 2)) * 3
                     + (wi  < Ww - WIN ? 0 : (wi  < Ww - SHIFT ? 1 : 2));
            int regj = (hj  < Hh - WIN ? 0 : (hj  < Hh - SHIFT ? 1 : 2)) * 3
                     + (wj  < Ww - WIN ? 0 : (wj  < Ww - SHIFT ? 1 : 2));
            if (regi != regj) v -= 100.0f;
        }
        tbl[(size_t)blockIdx.x * 4096 + idx] = v;
    }
}

// ---------------- LayerNorm, warp-per-row (4 rows / 128-thread block) -------
template<bool SHIFTED, typename TIN>
__global__ __launch_bounds__(128)
void ln_kernel(const TIN* __restrict__ x, const float* __restrict__ gw,
               const float* __restrict__ gb, f16* __restrict__ o)
{
    int warp = threadIdx.x >> 5, lane = threadIdx.x & 31;
    int row = blockIdx.x * 4 + warp;
    int src;
    if (SHIFTED) {
        int win = row / NN, pos = row % NN;
        int b = win >> 6, wh = (win >> 3) & 7, ww = win & 7;
        int i = pos / WIN, j = pos % WIN;
        int h = (wh * WIN + i + SHIFT) % Hh;
        int w = (ww * WIN + j + SHIFT) % Ww;
        src = (b * Hh + h) * Ww + w;
    } else {
        src = row;
    }
    const TIN* xr = x + (size_t)src * Cc;
    float v[12];
    float s = 0.0f, sq = 0.0f;
    #pragma unroll
    for (int k = 0; k < 12; k++) {
        v[k] = ld_as_float(xr + lane + k * 32);
        s  += v[k];
        sq += v[k] * v[k];
    }
    #pragma unroll
    for (int o2 = 16; o2; o2 >>= 1) {
        s  += __shfl_xor_sync(0xffffffffu, s,  o2);
        sq += __shfl_xor_sync(0xffffffffu, sq, o2);
    }
    float mean = s * (1.0f / Cc);
    float var  = sq * (1.0f / Cc) - mean * mean;
    float rstd = rsqrtf(var + 1e-5f);
    size_t ro = (size_t)row * Cc;
    #pragma unroll
    for (int k = 0; k < 12; k++) {
        int c = lane + k * 32;
        o[ro + c] = __float2half((v[k] - mean) * rstd * gw[c] + gb[c]);
    }
}

// ---------------- HMMA GEMM: out[M,N] = A[M,K](f16) @ W^T (W as [N][K] f16) -
// Proven-best R10 config: 128x128 CTA tile, BK=32, ROWB=80, 4 stages. FROZEN.
#define BK      32
#define STAGES  4
#define ROWB    80
#define STG_B   10240
#define STG     20480
#define SMEM_GEMM (STAGES * STG)    // 81920

enum { EPI_BIAS = 0, EPI_GELU = 1, EPI_RES = 2, EPI_SWIN = 3, EPI_BIASH = 4 };

template<int EPI>
__global__ __launch_bounds__(256, 2)
void hgemm(const f16* __restrict__ A, const f16* __restrict__ Bw,
           const float* __restrict__ bias, const float* __restrict__ res,
           const f16* __restrict__ resh,
           float* __restrict__ out, f16* __restrict__ oh,
           int M, int N, int K)
{
    extern __shared__ char smem[];
    uint32_t sb = smem_u32(smem);
    int tid = threadIdx.x, lane = tid & 31, warp = tid >> 5;
    int warpM = warp >> 2, warpN = warp & 3;      // 2 x 4 warp grid
    int mBase = blockIdx.y * 128, nBase = blockIdx.x * 128;
    const int nt = K / BK;

    float acc[4][4][4] = {};

    auto load_tile = [&](int t) {
        uint32_t st = sb + (t % STAGES) * STG;
        int k0 = t * BK;
        #pragma unroll
        for (int i = 0; i < 2; i++) {
            int ci = i * 256 + tid;
            int row = ci >> 2, c = ci & 3;
            cp16(st + row * ROWB + c * 16,
                 A + (size_t)(mBase + row) * K + k0 + c * 8);
        }
        #pragma unroll
        for (int i = 0; i < 2; i++) {
            int ci = i * 256 + tid;
            int row = ci >> 2, c = ci & 3;
            cp16(st + STG_B + row * ROWB + c * 16,
                 Bw + (size_t)(nBase + row) * K + k0 + c * 8);
        }
        CP_COMMIT();
    };

    load_tile(0);
    load_tile(1);
    load_tile(2);

    int aRow = warpM * 64 + (lane & 15);
    int aKb  = (lane >> 4) << 4;
    int bRow = warpN * 32 + ((lane >> 4) << 3) + (lane & 7);
    int bKb  = (lane & 8) << 1;

    for (int t = 0; t < nt; t++) {
        CP_WAIT(2);
        __syncthreads();
        if (t + 3 < nt) load_tile(t + 3);
        else            CP_COMMIT();            // keep group count invariant
        uint32_t st = sb + (t % STAGES) * STG;
        #pragma unroll
        for (int s = 0; s < 2; s++) {
            uint32_t a[4][4], b[4][2];
            #pragma unroll
            for (int i = 0; i < 4; i++) {
                uint32_t ad = st + (uint32_t)(aRow + i * 16) * ROWB + s * 32 + aKb;
                LDSM4(a[i], ad);
            }
            #pragma unroll
            for (int nf = 0; nf < 2; nf++) {
                uint32_t bt[4];
                uint32_t ad = st + STG_B + (uint32_t)(bRow + nf * 16) * ROWB + s * 32 + bKb;
                LDSM4(bt, ad);
                b[2*nf][0] = bt[0]; b[2*nf][1] = bt[1];
                b[2*nf+1][0] = bt[2]; b[2*nf+1][1] = bt[3];
            }
            #pragma unroll
            for (int i = 0; i < 4; i++)
                #pragma unroll
                for (int j = 0; j < 4; j++)
                    mma16816(acc[i][j], a[i], b[j]);
        }
    }

    // epilogue from registers
    int rBase = mBase + warpM * 64 + (lane >> 2);
    int cBase = nBase + warpN * 32 + (lane & 3) * 2;
    #pragma unroll
    for (int i = 0; i < 4; i++) {
        #pragma unroll
        for (int hh = 0; hh < 2; hh++) {
            int row = rBase + i * 16 + hh * 8;
            size_t orow;
            if (EPI == EPI_SWIN) {
                int win = row / NN, pos = row % NN;
                int b = win >> 6, wh = (win >> 3) & 7, ww = win & 7;
                int i2 = pos / WIN, j2 = pos % WIN;
                int h = (wh * WIN + i2 + SHIFT) % Hh;
                int w = (ww * WIN + j2 + SHIFT) % Ww;
                orow = (size_t)((b * Hh + h) * Ww + w);
            } else {
                orow = (size_t)row;
            }
            #pragma unroll
            for (int j = 0; j < 4; j++) {
                int col = cBase + j * 8;
                float v0 = acc[i][j][hh * 2 + 0] + bias[col];
                float v1 = acc[i][j][hh * 2 + 1] + bias[col + 1];
                if (EPI == EPI_GELU) {
                    v0 = 0.5f * v0 * (1.0f + erff(v0 * 0.70710678118654752f));
                    v1 = 0.5f * v1 * (1.0f + erff(v1 * 0.70710678118654752f));
                    *reinterpret_cast<__half2*>(&oh[orow * N + col]) =
                        __floats2half2_rn(v0, v1);
                } else if (EPI == EPI_BIASH) {
                    *reinterpret_cast<__half2*>(&oh[orow * N + col]) =
                        __floats2half2_rn(v0, v1);
                } else if (EPI == EPI_SWIN) {
                    const float2 r = *reinterpret_cast<const float2*>(&res[orow * Cc + col]);
                    v0 += r.x; v1 += r.y;
                    *reinterpret_cast<__half2*>(&oh[orow * N + col]) =
                        __floats2half2_rn(v0, v1);
                } else {
                    if (EPI == EPI_RES) {
                        __half2 rh = *reinterpret_cast<const __half2*>(&resh[orow * N + col]);
                        float2 rf = __half22float2(rh);
                        v0 += rf.x; v1 += rf.y;
                    }
                    float2 o2; o2.x = v0; o2.y = v1;
                    *reinterpret_cast<float2*>(&out[orow * N + col]) = o2;
                }
            }
        }
    }
}

// ---------------- windowed attention: mma + register softmax (best) ---------
#define AVS 0
#define AQS 5120
#define AKS 10240

__global__ __launch_bounds__(128)
void attn_kernel(const f16* __restrict__ qkv, const float* __restrict__ tbl,
                 f16* __restrict__ o)
{
    __shared__ __align__(16) char sm[15360];
    uint32_t sb = smem_u32(sm);
    int hd = blockIdx.x, win = blockIdx.y;
    int wh = (win >> 3) & 7, ww = win & 7;
    int cls = ((wh == 7) ? 2 : 0) | ((ww == 7) ? 1 : 0);
    int tid = threadIdx.x, lane = tid & 31, w = tid >> 5;

    // ---- load q/k/v (49 rows x 32 halves), zero pad rows 49..63 ----
    {
        const f16* base = qkv + (size_t)win * NN * (3 * Cc) + hd * DH;
        #pragma unroll
        for (int it = 0; it < 6; it++) {
            int idx = it * 128 + tid;           // 0..767
            int mat = idx >> 8, loc = idx & 255;
            int row = loc >> 2, ch = loc & 3;
            int soff = (mat == 0) ? AQS : (mat == 1) ? AKS : AVS;
            uint4 val = make_uint4(0u, 0u, 0u, 0u);
            if (row < NN)
                val = *reinterpret_cast<const uint4*>(base + (size_t)row * (3 * Cc) + mat * Cc + ch * 8);
            *reinterpret_cast<uint4*>(sm + soff + row * 80 + ch * 16) = val;
        }
    }
    __syncthreads();

    // ---- S = Q @ K^T ----
    float acc[8][4] = {};
    #pragma unroll
    for (int s = 0; s < 2; s++) {
        uint32_t a[4];
        LDSM4(a, sb + AQS + (uint32_t)(w * 16 + (lane & 15)) * 80 + ((lane >> 4) << 4) + s * 32);
        #pragma unroll
        for (int nf = 0; nf < 4; nf++) {
            uint32_t b[4];
            LDSM4(b, sb + AKS + (uint32_t)(nf * 16 + ((lane >> 4) << 3) + (lane & 7)) * 80
                        + ((lane & 8) << 1) + s * 32);
            mma16816(acc[2 * nf],     a, b);
            mma16816(acc[2 * nf + 1], a, b + 2);
        }
    }

    // ---- scale + bias + mask from table ----
    {
        const float2* tb = reinterpret_cast<const float2*>(
            tbl + ((size_t)(cls * HEADS + hd) << 12));
        int r0 = w * 16 + (lane >> 2), cq = lane & 3;
        #pragma unroll
        for (int j = 0; j < 8; j++) {
            float2 t0 = tb[r0 * 32 + j * 4 + cq];
            float2 t1 = tb[(r0 + 8) * 32 + j * 4 + cq];
            acc[j][0] = fmaf(acc[j][0], SCALE, t0.x);
            acc[j][1] = fmaf(acc[j][1], SCALE, t0.y);
            acc[j][2] = fmaf(acc[j][2], SCALE, t1.x);
            acc[j][3] = fmaf(acc[j][3], SCALE, t1.y);
        }
    }

    // ---- softmax in registers ----
    #pragma unroll
    for (int hh = 0; hh < 2; hh++) {
        float mx = -1e30f;
        #pragma unroll
        for (int j = 0; j < 8; j++)
            mx = fmaxf(mx, fmaxf(acc[j][2 * hh], acc[j][2 * hh + 1]));
        mx = fmaxf(mx, __shfl_xor_sync(0xffffffffu, mx, 1));
        mx = fmaxf(mx, __shfl_xor_sync(0xffffffffu, mx, 2));
        float sum = 0.0f;
        #pragma unroll
        for (int j = 0; j < 8; j++) {
            float e0 = __expf(acc[j][2 * hh]     - mx);
            float e1 = __expf(acc[j][2 * hh + 1] - mx);
            acc[j][2 * hh] = e0; acc[j][2 * hh + 1] = e1;
            sum += e0 + e1;
        }
        sum += __shfl_xor_sync(0xffffffffu, sum, 1);
        sum += __shfl_xor_sync(0xffffffffu, sum, 2);
        float inv = 1.0f / sum;
        #pragma unroll
        for (int j = 0; j < 8; j++) {
            acc[j][2 * hh] *= inv; acc[j][2 * hh + 1] *= inv;
        }
    }

    // ---- repack P: C-fragment (f32) -> A-fragment (f16) ----
    uint32_t pa[4][4];
    #pragma unroll
    for (int jj = 0; jj < 4; jj++) {
        pa[jj][0] = pack_h2(acc[2 * jj][0],     acc[2 * jj][1]);
        pa[jj][1] = pack_h2(acc[2 * jj][2],     acc[2 * jj][3]);
        pa[jj][2] = pack_h2(acc[2 * jj + 1][0], acc[2 * jj + 1][1]);
        pa[jj][3] = pack_h2(acc[2 * jj + 1][2], acc[2 * jj + 1][3]);
    }

    // ---- O = P @ V ----
    float oc[4][4] = {};
    int g = lane >> 3;
    #pragma unroll
    for (int ks = 0; ks < 4; ks++) {
        #pragma unroll
        for (int ng = 0; ng < 2; ng++) {
            uint32_t b[4];
            LDSM4T(b, sb + AVS + (uint32_t)(ks * 16 + (g & 1) * 8 + (lane & 7)) * 80
                         + (ng * 16 + (g >> 1) * 8) * 2);
            mma16816(oc[2 * ng],     pa[ks], b);
            mma16816(oc[2 * ng + 1], pa[ks], b + 2);
        }
    }

    // ---- write output ----
    {
        f16* ob = o + (size_t)win * NN * Cc + hd * DH;
        int r0 = w * 16 + (lane >> 2), c0 = (lane & 3) * 2;
        #pragma unroll
        for (int hh = 0; hh < 2; hh++) {
            int row = r0 + hh * 8;
            if (row < NN) {
                #pragma unroll
                for (int j = 0; j < 4; j++) {
                    __half2 hv = __floats2half2_rn(oc[j][hh * 2], oc[j][hh * 2 + 1]);
                    *reinterpret_cast<__half2*>(ob + (size_t)row * Cc + j * 8 + c0) = hv;
                }
            }
        }
    }
}

// ---------------- launcher --------------------------------------------------
extern "C" void kernel_launch(void* const* d_in, const int* in_sizes, int n_in,
                              void* d_out, int out_size)
{
    const float* x      = (const float*)d_in[0];
    const float* n1w    = (const float*)d_in[1];
    const float* n1b    = (const float*)d_in[2];
    const float* qkv_w  = (const float*)d_in[3];
    const float* qkv_b  = (const float*)d_in[4];
    const float* proj_w = (const float*)d_in[5];
    const float* proj_b = (const float*)d_in[6];
    const float* rpb    = (const float*)d_in[7];
    const float* n2w    = (const float*)d_in[8];
    const float* n2b    = (const float*)d_in[9];
    const float* fc1_w  = (const float*)d_in[10];
    const float* fc1_b  = (const float*)d_in[11];
    const float* fc2_w  = (const float*)d_in[12];
    const float* fc2_b  = (const float*)d_in[13];
    float* out = (float*)d_out;

    f16 *a, *f, *w, *qkvh, *x1h;
    float *tbl;
    cudaGetSymbolAddress((void**)&a,    g_a);
    cudaGetSymbolAddress((void**)&f,    g_f);
    cudaGetSymbolAddress((void**)&w,    g_w);
    cudaGetSymbolAddress((void**)&qkvh, g_qkvh);
    cudaGetSymbolAddress((void**)&x1h,  g_x1h);
    cudaGetSymbolAddress((void**)&tbl,  g_tbl);

    cudaFuncSetAttribute(hgemm<EPI_BIASH>, cudaFuncAttributeMaxDynamicSharedMemorySize, SMEM_GEMM);
    cudaFuncSetAttribute(hgemm<EPI_SWIN>,  cudaFuncAttributeMaxDynamicSharedMemorySize, SMEM_GEMM);
    cudaFuncSetAttribute(hgemm<EPI_GELU>,  cudaFuncAttributeMaxDynamicSharedMemorySize, SMEM_GEMM);
    cudaFuncSetAttribute(hgemm<EPI_RES>,   cudaFuncAttributeMaxDynamicSharedMemorySize, SMEM_GEMM);

    const int MT = NTOK / 128;  // 784

    // 0) fused weight transposes (single launch) + bias/mask table
    wconv_all<<<T_TOT, 256>>>(qkv_w, proj_w, fc1_w, fc2_w, w);
    attn_tbl<<<4 * HEADS, 256>>>(rpb, tbl);

    // 1) LN1 + shift + window partition -> fp16 (warp-per-row)
    ln_kernel<true, float><<<NTOK / 4, 128>>>(x, n1w, n1b, a);
    // 2) QKV GEMM -> fp16 qkv (+bias)
    hgemm<EPI_BIASH><<<dim3(1152 / 128, MT), 256, SMEM_GEMM>>>(
        a, w + WOFF_QKV, qkv_b, nullptr, nullptr, nullptr, qkvh, NTOK, 1152, Cc);
    // 3) attention (1 head/block) -> fp16 (A of proj)
    attn_kernel<<<dim3(HEADS, Bz * NWIN), 128>>>(qkvh, tbl, a);
    // 4) proj GEMM + swin remap + residual(x fp32) -> fp16 x1
    hgemm<EPI_SWIN><<<dim3(Cc / 128, MT), 256, SMEM_GEMM>>>(
        a, w + WOFF_PROJ, proj_b, x, nullptr, nullptr, x1h, NTOK, Cc, Cc);
    // 5) LN2 (fp16 input, warp-per-row) -> fp16
    ln_kernel<false, f16><<<NTOK / 4, 128>>>(x1h, n2w, n2b, a);
    // 6) FC1 GEMM + GELU -> fp16 (A of FC2)
    hgemm<EPI_GELU><<<dim3(HID / 128, MT), 256, SMEM_GEMM>>>(
        a, w + WOFF_FC1, fc1_b, nullptr, nullptr, nullptr, f, NTOK, HID, Cc);
    // 7) FC2 GEMM + residual(x1 fp16) -> fp32 out
    hgemm<EPI_RES><<<dim3(Cc / 128, MT), 256, SMEM_GEMM>>>(
        f, w + WOFF_FC2, fc2_b, nullptr, x1h, out, nullptr, NTOK, Cc, HID);
}